// round 2
// baseline (speedup 1.0000x reference)
#include <cuda_runtime.h>
#include <math_constants.h>

// HierSoftmaxNLL: b-ary array tree (branch=16), parent(i) = (i-1)>>4.
// For this tree flat_index == [0..N-2] and child_index == [1..N-1], so
// log_cond_p[node j] = log_softmax over its sibling group of scores[:, j-1],
// and log_prob at a leaf = sum of log_cond_p along the root->leaf path.
// Output = mean over batch of -log_prob[label leaf].
// NOTE: jax x64 is disabled, so labels / label_order are int32 on device.

#define BRANCH 16

__global__ void hiersoftmax_nll_kernel(const float* __restrict__ scores,
                                       const int*   __restrict__ labels,
                                       const int*   __restrict__ label_order,
                                       float* __restrict__ out,
                                       int n_scores_per_row,  // N_NODES - 1 = 9999
                                       int batch,             // 1024
                                       int n_leaves)          // label_order length
{
    int b = threadIdx.x;
    float total = 0.0f;

    if (b < batch) {
        const float* row = scores + (size_t)b * (size_t)n_scores_per_row;

        int lbl = labels[b];
        lbl = max(0, min(lbl, n_leaves - 1));          // safety clamp
        int node = label_order[lbl];
        node = max(0, min(node, n_scores_per_row));    // node in [0, N-1]

        while (node > 0) {
            int g    = (node - 1) >> 4;       // parent / group id
            int pos  = (node - 1) & 15;       // position within sibling group
            int base = g << 4;                // first score index of group
            int cnt  = n_scores_per_row - base;
            if (cnt > BRANCH) cnt = BRANCH;

            float v[BRANCH];
            #pragma unroll
            for (int k = 0; k < BRANCH; ++k) {
                v[k] = (k < cnt) ? __ldg(row + base + k) : -CUDART_INF_F;
            }

            float m = v[0];
            #pragma unroll
            for (int k = 1; k < BRANCH; ++k) m = fmaxf(m, v[k]);

            float s = 0.0f;
            #pragma unroll
            for (int k = 0; k < BRANCH; ++k) {
                if (k < cnt) s += __expf(v[k] - m);
            }

            total += v[pos] - (m + __logf(s));
            node = g;   // parent
        }
    }

    // Block-wide reduction of -total (blockDim.x == 1024, power of 2)
    __shared__ float sdata[1024];
    sdata[threadIdx.x] = (b < batch) ? -total : 0.0f;
    __syncthreads();

    for (int stride = blockDim.x >> 1; stride > 0; stride >>= 1) {
        if (threadIdx.x < stride) sdata[threadIdx.x] += sdata[threadIdx.x + stride];
        __syncthreads();
    }

    if (threadIdx.x == 0) {
        out[0] = sdata[0] / (float)batch;
    }
}

extern "C" void kernel_launch(void* const* d_in, const int* in_sizes, int n_in,
                              void* d_out, int out_size) {
    // Input order (metadata): scores, labels, flat_index, child_index,
    //                         anc_matrix, label_order, num_internal, max_children
    const float* scores      = (const float*)d_in[0];
    const int*   labels      = (const int*)d_in[1];
    const int*   label_order = (const int*)d_in[5];
    float*       out         = (float*)d_out;

    int batch = in_sizes[1];                      // 1024
    int n_scores_per_row = in_sizes[0] / batch;   // 9999
    int n_leaves = in_sizes[5];

    hiersoftmax_nll_kernel<<<1, 1024>>>(scores, labels, label_order, out,
                                        n_scores_per_row, batch, n_leaves);
}

// round 4
// speedup vs baseline: 2.3217x; 2.3217x over previous
#include <cuda_runtime.h>
#include <math_constants.h>

// HierSoftmaxNLL: 16-ary array tree, parent(i) = (i-1)>>4.
// flat_index == [0..N-2], child_index == [1..N-1]  =>
// log_cond_p[node j] = log_softmax over its sibling group of scores[:, j-1];
// leaf log-prob = sum of log_cond_p along root->leaf path.
// Output = mean over batch of -leaf_log_prob[label].
//
// 16 lanes per batch row; one coalesced LDG per tree level; logsumexp via
// xor-shuffles. FIXED 4-iteration loop (max tree depth) keeps both 16-lane
// groups of each warp converged so full-mask shuffles are legal.

#define LANES_PER_ROW 16
#define BLOCK_THREADS 256
#define ROWS_PER_BLOCK (BLOCK_THREADS / LANES_PER_ROW)   // 16
#define MAX_BLOCKS 1024
#define MAX_DEPTH 4

__device__ float g_partials[MAX_BLOCKS];

__global__ void hiersoftmax_path_kernel(const float* __restrict__ scores,
                                        const int*   __restrict__ labels,
                                        const int*   __restrict__ label_order,
                                        int n_scores_per_row,  // 9999
                                        int batch,             // 1024
                                        int n_leaves)
{
    const int tid  = threadIdx.x;
    const int lane = tid & (LANES_PER_ROW - 1);          // 0..15 within group
    const int rowb = tid >> 4;                           // row within block
    const int b    = blockIdx.x * ROWS_PER_BLOCK + rowb; // batch row
    const bool row_valid = (b < batch);

    const float* row = scores + (size_t)(row_valid ? b : 0) * (size_t)n_scores_per_row;

    int node = 0;
    if (row_valid) {
        int lbl = labels[b];
        lbl = max(0, min(lbl, n_leaves - 1));
        node = label_order[lbl];
        node = max(0, min(node, n_scores_per_row));
    }

    float total = 0.0f;

    #pragma unroll
    for (int it = 0; it < MAX_DEPTH; ++it) {
        const bool active = (node > 0);
        const int nd   = active ? node : 1;     // safe dummy when inactive
        const int g    = (nd - 1) >> 4;
        const int pos  = (nd - 1) & 15;
        const int base = g << 4;
        const int idx  = base + lane;

        float v = (active && idx < n_scores_per_row) ? __ldg(row + idx)
                                                     : -CUDART_INF_F;

        // 16-lane max (xor shuffles stay within the 16-lane group; all 32
        // lanes of the warp are converged here, so full mask is legal)
        float m = v;
        #pragma unroll
        for (int s = 1; s < LANES_PER_ROW; s <<= 1)
            m = fmaxf(m, __shfl_xor_sync(0xFFFFFFFFu, m, s));

        float sum = (v == -CUDART_INF_F) ? 0.0f : __expf(v - m);
        #pragma unroll
        for (int s = 1; s < LANES_PER_ROW; s <<= 1)
            sum += __shfl_xor_sync(0xFFFFFFFFu, sum, s);

        if (active && lane == pos)
            total += v - (m + __logf(sum));

        node = active ? g : 0;
    }

    // Sum the single contributing lane's totals across the 16-lane group
    #pragma unroll
    for (int s = 1; s < LANES_PER_ROW; s <<= 1)
        total += __shfl_xor_sync(0xFFFFFFFFu, total, s);

    __shared__ float srow[ROWS_PER_BLOCK];
    if (lane == 0) srow[rowb] = row_valid ? -total : 0.0f;
    __syncthreads();

    if (tid == 0) {
        float acc = 0.0f;
        #pragma unroll
        for (int r = 0; r < ROWS_PER_BLOCK; ++r) acc += srow[r];
        g_partials[blockIdx.x] = acc;
    }
}

__global__ void hiersoftmax_reduce_kernel(float* __restrict__ out,
                                          int n_blocks, int batch)
{
    __shared__ float sdata[256];
    int tid = threadIdx.x;
    float acc = 0.0f;
    for (int i = tid; i < n_blocks; i += blockDim.x) acc += g_partials[i];
    sdata[tid] = acc;
    __syncthreads();
    for (int stride = blockDim.x >> 1; stride > 0; stride >>= 1) {
        if (tid < stride) sdata[tid] += sdata[tid + stride];
        __syncthreads();
    }
    if (tid == 0) out[0] = sdata[0] / (float)batch;
}

extern "C" void kernel_launch(void* const* d_in, const int* in_sizes, int n_in,
                              void* d_out, int out_size) {
    // Inputs: scores, labels, flat_index, child_index, anc_matrix,
    //         label_order, num_internal, max_children
    const float* scores      = (const float*)d_in[0];
    const int*   labels      = (const int*)d_in[1];
    const int*   label_order = (const int*)d_in[5];
    float*       out         = (float*)d_out;

    int batch = in_sizes[1];                      // 1024
    int n_scores_per_row = in_sizes[0] / batch;   // 9999
    int n_leaves = in_sizes[5];

    int n_blocks = (batch + ROWS_PER_BLOCK - 1) / ROWS_PER_BLOCK;  // 64
    if (n_blocks > MAX_BLOCKS) n_blocks = MAX_BLOCKS;

    hiersoftmax_path_kernel<<<n_blocks, BLOCK_THREADS>>>(
        scores, labels, label_order, n_scores_per_row, batch, n_leaves);
    hiersoftmax_reduce_kernel<<<1, 256>>>(out, n_blocks, batch);
}